// round 10
// baseline (speedup 1.0000x reference)
#include <cuda_runtime.h>
#include <cuda_fp16.h>
#include <math.h>
#include <cstdint>

// ---------------------------------------------------------------------------
// Problem constants
// ---------------------------------------------------------------------------
static constexpr int BATCH = 2;
static constexpr int CDIM  = 256;
static constexpr int TSEQ  = 4096;   // 64*64
// 64^-0.25 * sqrt(log2(e)) : folds the exp->exp2 conversion into Q and K
static constexpr float QK_SCALE = 0.42466090936113257f;
static constexpr int NTILES = TSEQ / 64;  // 64 kv tiles of 64 keys

// Scratch (device globals; allocation-free)
__device__ __half g_xnh[BATCH * TSEQ * CDIM];  // GN out, [b][t][c] 4 MB
__device__ __half g_hh [BATCH * TSEQ * CDIM];  // attn out, [b][t][c] 4 MB
__device__ __half g_qh[8 * TSEQ * 64];         // [bh][t][c] 4 MB
__device__ __half g_kh[8 * TSEQ * 64];         // [bh][t][c] 4 MB
__device__ __half g_vh[8 * 64 * TSEQ];         // [bh][d][t] 4 MB
__device__ __half g_wqkvh[768 * 256];          // fp16 qkv weight
__device__ __half g_wprojh[256 * 256];         // fp16 proj weight
__device__ float g_mean[64];
__device__ float g_rstd[64];

// ---------------------------------------------------------------------------
// PTX helpers (sm_80+ subset: mma.sync / ldmatrix / cp.async)
// ---------------------------------------------------------------------------
__device__ __forceinline__ uint32_t smem_to_u32(const void* p) {
    uint32_t a;
    asm("{ .reg .u64 t; cvta.to.shared.u64 t, %1; cvt.u32.u64 %0, t; }" : "=r"(a) : "l"(p));
    return a;
}

__device__ __forceinline__ void cp_async16(uint32_t saddr, const void* gaddr) {
    asm volatile("cp.async.cg.shared.global [%0], [%1], 16;" :: "r"(saddr), "l"(gaddr));
}
__device__ __forceinline__ void cp_commit() { asm volatile("cp.async.commit_group;"); }
template <int N>
__device__ __forceinline__ void cp_wait() { asm volatile("cp.async.wait_group %0;" :: "n"(N)); }

__device__ __forceinline__ void ldm_x4(uint32_t* r, uint32_t addr) {
    asm volatile("ldmatrix.sync.aligned.m8n8.x4.shared.b16 {%0,%1,%2,%3}, [%4];"
        : "=r"(r[0]), "=r"(r[1]), "=r"(r[2]), "=r"(r[3]) : "r"(addr));
}

__device__ __forceinline__ void mma_f16(float* c, const uint32_t* a, uint32_t b0, uint32_t b1) {
    asm volatile("mma.sync.aligned.m16n8k16.row.col.f32.f16.f16.f32 "
        "{%0,%1,%2,%3}, {%4,%5,%6,%7}, {%8,%9}, {%0,%1,%2,%3};"
        : "+f"(c[0]), "+f"(c[1]), "+f"(c[2]), "+f"(c[3])
        : "r"(a[0]), "r"(a[1]), "r"(a[2]), "r"(a[3]), "r"(b0), "r"(b1));
}

// f16 accumulator variant: D/C are 2 packed f16x2 regs.
// c[0] = (row r, cols 2c,2c+1), c[1] = (row r+8, cols 2c,2c+1)
__device__ __forceinline__ void mma_f16acc(uint32_t* c, const uint32_t* a, uint32_t b0, uint32_t b1) {
    asm volatile("mma.sync.aligned.m16n8k16.row.col.f16.f16.f16.f16 "
        "{%0,%1}, {%2,%3,%4,%5}, {%6,%7}, {%0,%1};"
        : "+r"(c[0]), "+r"(c[1])
        : "r"(a[0]), "r"(a[1]), "r"(a[2]), "r"(a[3]), "r"(b0), "r"(b1));
}

__device__ __forceinline__ uint32_t pack_f16x2(float lo, float hi) {
    uint32_t r;
    asm("cvt.rn.f16x2.f32 %0, %1, %2;" : "=r"(r) : "f"(hi), "f"(lo));
    return r;
}
__device__ __forceinline__ uint32_t ex2_f16x2(uint32_t a) {
    uint32_t r;
    asm("ex2.approx.f16x2 %0, %1;" : "=r"(r) : "r"(a));
    return r;
}
__device__ __forceinline__ uint32_t hadd2(uint32_t a, uint32_t b) {
    uint32_t r;
    asm("add.f16x2 %0, %1, %2;" : "=r"(r) : "r"(a), "r"(b));
    return r;
}

// ---------------------------------------------------------------------------
// GroupNorm stats: one block per (batch, group)
// ---------------------------------------------------------------------------
__global__ void gn_stats_kernel(const float* __restrict__ x) {
    int bg = blockIdx.x;
    const float4* p = (const float4*)(x + (size_t)bg * 32768);
    float s = 0.f, s2 = 0.f;
    for (int i = threadIdx.x; i < 8192; i += 256) {
        float4 v = p[i];
        s  += v.x + v.y + v.z + v.w;
        s2 += v.x*v.x + v.y*v.y + v.z*v.z + v.w*v.w;
    }
    #pragma unroll
    for (int off = 16; off; off >>= 1) {
        s  += __shfl_xor_sync(0xffffffffu, s,  off);
        s2 += __shfl_xor_sync(0xffffffffu, s2, off);
    }
    __shared__ float as[8], bs[8];
    int w = threadIdx.x >> 5, lane = threadIdx.x & 31;
    if (lane == 0) { as[w] = s; bs[w] = s2; }
    __syncthreads();
    if (threadIdx.x == 0) {
        float ts = 0.f, t2 = 0.f;
        #pragma unroll
        for (int i = 0; i < 8; i++) { ts += as[i]; t2 += bs[i]; }
        float mu  = ts * (1.f / 32768.f);
        float var = t2 * (1.f / 32768.f) - mu * mu;
        g_mean[bg] = mu;
        g_rstd[bg] = rsqrtf(var + 1e-5f);
    }
}

// ---------------------------------------------------------------------------
// GroupNorm apply + transpose: x [b][c][t] fp32 -> g_xnh [b][t][c] fp16.
// ---------------------------------------------------------------------------
__global__ void gn_apply_t_kernel(const float* __restrict__ x,
                                  const float* __restrict__ w,
                                  const float* __restrict__ b) {
    __shared__ float tile[64][68];
    int b_ = blockIdx.z, c0 = blockIdx.x * 64, t0 = blockIdx.y * 64;

    #pragma unroll
    for (int p = 0; p < 4; p++) {
        int i = threadIdx.x + p * 256;
        int c = i >> 4, t4 = (i & 15) * 4;
        int cg = c0 + c;
        int bg = b_ * 32 + (cg >> 3);
        float sw = w[cg] * g_rstd[bg];
        float sb = b[cg] - g_mean[bg] * sw;
        float4 v = *(const float4*)&x[((size_t)(b_ * CDIM + cg)) * TSEQ + t0 + t4];
        tile[c][t4 + 0] = v.x * sw + sb;
        tile[c][t4 + 1] = v.y * sw + sb;
        tile[c][t4 + 2] = v.z * sw + sb;
        tile[c][t4 + 3] = v.w * sw + sb;
    }
    __syncthreads();

    #pragma unroll
    for (int p = 0; p < 8; p++) {
        int i = threadIdx.x + p * 256;
        int t = i >> 5, cp = (i & 31) * 2;
        uint32_t u = pack_f16x2(tile[cp][t], tile[cp + 1][t]);
        *(uint32_t*)&g_xnh[((size_t)(b_ * TSEQ + t0 + t)) * CDIM + c0 + cp] = u;
    }
}

// ---------------------------------------------------------------------------
// Weight fp32 -> fp16
// ---------------------------------------------------------------------------
__global__ void wconv_kernel(const float* __restrict__ qkvw,
                             const float* __restrict__ projw) {
    int idx = blockIdx.x * 256 + threadIdx.x;   // 0..196607
    g_wqkvh[idx] = __float2half(qkvw[idx]);
    if (idx < 65536) g_wprojh[idx] = __float2half(projw[idx]);
}

// ---------------------------------------------------------------------------
// Shared fp16 TN GEMM mainloop, 128(t) x 64(o) tile, 4 warps x 32 t-rows:
// each B ldmatrix feeds FOUR MMAs (two A-fragment sets). K=256 in 4
// double-buffered cp.async chunks of 64. Stage = A 16KB + B 8KB = 24KB.
// ---------------------------------------------------------------------------
__device__ __forceinline__ void gemm_mainloop2(
    uint32_t sb, const char* Ag, const char* Bg,
    float (*s0)[4], float (*s1)[4]) {
    const int tid = threadIdx.x, lane = tid & 31, wid = tid >> 5;
    const int r0    = wid * 32 + (lane & 7) + (((lane >> 3) & 1) << 3);
    const int cbitA = lane >> 4;
    const int rowB  = (lane & 7) + ((lane >> 4) << 3);
    const int cbitB = (lane >> 3) & 1;
    const uint32_t brow = rowB * 128;

    #pragma unroll
    for (int nt = 0; nt < 8; nt++)
        #pragma unroll
        for (int i = 0; i < 4; i++) { s0[nt][i] = 0.f; s1[nt][i] = 0.f; }

    auto issue = [&](int kc) {
        uint32_t dst = sb + (uint32_t)(kc & 1) * 24576;
        #pragma unroll
        for (int p = 0; p < 8; p++) {                 // A: 128 rows x 128B
            int i = tid + p * 128;
            int row = i >> 3, c = i & 7;
            uint32_t soff = row * 128 + ((c ^ (row & 7)) * 16);
            cp_async16(dst + soff, Ag + (size_t)row * 512 + kc * 128 + c * 16);
        }
        #pragma unroll
        for (int p = 0; p < 4; p++) {                 // B: 64 rows x 128B
            int i = tid + p * 128;
            int row = i >> 3, c = i & 7;
            uint32_t soff = row * 128 + ((c ^ (row & 7)) * 16);
            cp_async16(dst + 16384 + soff, Bg + (size_t)row * 512 + kc * 128 + c * 16);
        }
        cp_commit();
    };

    issue(0);
    #pragma unroll
    for (int kc = 0; kc < 4; kc++) {
        if (kc < 3) { issue(kc + 1); cp_wait<1>(); } else { cp_wait<0>(); }
        __syncthreads();
        uint32_t abase = sb + (uint32_t)(kc & 1) * 24576;
        uint32_t a0 = abase + r0 * 128;
        uint32_t a1 = abase + (r0 + 16) * 128;        // (r0+16)&7 == r0&7
        uint32_t kbase = abase + 16384 + brow;
        #pragma unroll
        for (int ks = 0; ks < 4; ks++) {
            uint32_t qa0[4], qa1[4];
            uint32_t co = (((ks * 2 + cbitA) ^ (r0 & 7)) << 4);
            ldm_x4(qa0, a0 + co);
            ldm_x4(qa1, a1 + co);
            uint32_t coffB = (((ks * 2 + cbitB) ^ (lane & 7)) << 4);
            #pragma unroll
            for (int nt2 = 0; nt2 < 4; nt2++) {
                uint32_t bfr[4];
                ldm_x4(bfr, kbase + nt2 * 2048 + coffB);
                mma_f16(s0[nt2 * 2 + 0], qa0, bfr[0], bfr[1]);
                mma_f16(s0[nt2 * 2 + 1], qa0, bfr[2], bfr[3]);
                mma_f16(s1[nt2 * 2 + 0], qa1, bfr[0], bfr[1]);
                mma_f16(s1[nt2 * 2 + 1], qa1, bfr[2], bfr[3]);
            }
        }
        __syncthreads();
    }
}

// ---------------------------------------------------------------------------
// QKV GEMM: 128t x 64o tiles. Epilogue routes to Q/K [bh][t][c] (scaled)
// directly from fragments, or V [bh][d][t] via smem transpose.
// ---------------------------------------------------------------------------
__global__ void __launch_bounds__(128)
gemm_qkv_h(const __half* __restrict__ Xt, const float* __restrict__ bias) {
    __shared__ __align__(128) char sm[49152];
    uint32_t sb = smem_to_u32(sm);
    int b_ = blockIdx.z, t0 = blockIdx.x * 128, o0 = blockIdx.y * 64;

    float s0[8][4], s1[8][4];
    gemm_mainloop2(sb,
        (const char*)(Xt + ((size_t)b_ * TSEQ + t0) * CDIM),
        (const char*)(g_wqkvh + (size_t)o0 * CDIM), s0, s1);

    const int lane = threadIdx.x & 31, wid = threadIdx.x >> 5;
    int q   = wid * 32 + (lane >> 2);
    int cc2 = (lane & 3) * 2;

    int h    = o0 / 192;
    int type = (o0 % 192) / 64;   // 0=Q 1=K 2=V
    int bh   = b_ * 4 + h;

    if (type < 2) {
        __half* dst = ((type == 0) ? g_qh : g_kh) + ((size_t)bh * TSEQ + t0) * 64;
        #pragma unroll
        for (int nt = 0; nt < 8; nt++) {
            int ol = nt * 8 + cc2;
            float b0 = bias[o0 + ol], b1 = bias[o0 + ol + 1];
            *(uint32_t*)&dst[(size_t)q * 64 + ol] =
                pack_f16x2((s0[nt][0] + b0) * QK_SCALE, (s0[nt][1] + b1) * QK_SCALE);
            *(uint32_t*)&dst[(size_t)(q + 8) * 64 + ol] =
                pack_f16x2((s0[nt][2] + b0) * QK_SCALE, (s0[nt][3] + b1) * QK_SCALE);
            *(uint32_t*)&dst[(size_t)(q + 16) * 64 + ol] =
                pack_f16x2((s1[nt][0] + b0) * QK_SCALE, (s1[nt][1] + b1) * QK_SCALE);
            *(uint32_t*)&dst[(size_t)(q + 24) * 64 + ol] =
                pack_f16x2((s1[nt][2] + b0) * QK_SCALE, (s1[nt][3] + b1) * QK_SCALE);
        }
    } else {
        __half (*sv)[136] = (__half(*)[136])sm;   // [64 o][128 t + pad]
        #pragma unroll
        for (int nt = 0; nt < 8; nt++) {
            int ol = nt * 8 + cc2;
            float b0 = bias[o0 + ol], b1 = bias[o0 + ol + 1];
            sv[ol][q]          = __float2half(s0[nt][0] + b0);
            sv[ol + 1][q]      = __float2half(s0[nt][1] + b1);
            sv[ol][q + 8]      = __float2half(s0[nt][2] + b0);
            sv[ol + 1][q + 8]  = __float2half(s0[nt][3] + b1);
            sv[ol][q + 16]     = __float2half(s1[nt][0] + b0);
            sv[ol + 1][q + 16] = __float2half(s1[nt][1] + b1);
            sv[ol][q + 24]     = __float2half(s1[nt][2] + b0);
            sv[ol + 1][q + 24] = __float2half(s1[nt][3] + b1);
        }
        __syncthreads();
        for (int i = threadIdx.x; i < 4096; i += 128) {
            int d = i >> 6, tp = (i & 63) * 2;
            uint32_t u = pack_f16x2(__half2float(sv[d][tp]), __half2float(sv[d][tp + 1]));
            *(uint32_t*)&g_vh[((size_t)bh * 64 + d) * TSEQ + t0 + tp] = u;
        }
    }
}

// ---------------------------------------------------------------------------
// Proj GEMM: 128t x 64o tiles + bias + residual, fp32 out [b][o][t].
// ---------------------------------------------------------------------------
__global__ void __launch_bounds__(128)
gemm_proj_h(const __half* __restrict__ Ht, const float* __restrict__ bias,
            const float* __restrict__ R, float* __restrict__ Y) {
    __shared__ __align__(128) char sm[49152];
    uint32_t sb = smem_to_u32(sm);
    int b_ = blockIdx.z, t0 = blockIdx.x * 128, o0 = blockIdx.y * 64;

    float s0[8][4], s1[8][4];
    gemm_mainloop2(sb,
        (const char*)(Ht + ((size_t)b_ * TSEQ + t0) * CDIM),
        (const char*)(g_wprojh + (size_t)o0 * CDIM), s0, s1);

    const int lane = threadIdx.x & 31, wid = threadIdx.x >> 5;
    int q   = wid * 32 + (lane >> 2);
    int cc2 = (lane & 3) * 2;

    float (*so)[132] = (float(*)[132])sm;   // [64 o][128 t + pad]
    #pragma unroll
    for (int nt = 0; nt < 8; nt++) {
        int ol = nt * 8 + cc2;
        so[ol][q]          = s0[nt][0];
        so[ol + 1][q]      = s0[nt][1];
        so[ol][q + 8]      = s0[nt][2];
        so[ol + 1][q + 8]  = s0[nt][3];
        so[ol][q + 16]     = s1[nt][0];
        so[ol + 1][q + 16] = s1[nt][1];
        so[ol][q + 24]     = s1[nt][2];
        so[ol + 1][q + 24] = s1[nt][3];
    }
    __syncthreads();
    for (int i = threadIdx.x; i < 2048; i += 128) {
        int o = i >> 5, t4 = (i & 31) * 4;
        size_t idx = ((size_t)(b_ * CDIM + o0 + o)) * TSEQ + t0 + t4;
        float4 rv = *(const float4*)&R[idx];
        float bvv = bias[o0 + o];
        float4 r;
        r.x = so[o][t4 + 0] + bvv + rv.x;
        r.y = so[o][t4 + 1] + bvv + rv.y;
        r.z = so[o][t4 + 2] + bvv + rv.z;
        r.w = so[o][t4 + 3] + bvv + rv.w;
        *(float4*)&Y[idx] = r;
    }
}

// ---------------------------------------------------------------------------
// Flash attention, fp16 mma.sync. 128-query tile, 4 warps, 32 q-rows/warp.
// S-GEMM uses f16 accumulators: D comes back packed f16x2 in exactly the
// P·V^T A-fragment layout, so softmax is just ex2.approx.f16x2 on the D regs
// (no cvt packs). O stays fp32. 3-stage cp.async pipeline, one sync/iter.
// ---------------------------------------------------------------------------
__global__ void __launch_bounds__(128, 3)
attn_mma_kernel(const __half* __restrict__ Qh,
                const __half* __restrict__ Kh,
                const __half* __restrict__ Vh,
                __half* __restrict__ houtT) {
    __shared__ __align__(128) char smem[49152];   // 3 stages x 16 KB
    uint32_t sb = smem_to_u32(smem);
    const int tid = threadIdx.x, lane = tid & 31, wid = tid >> 5;
    const int bh = blockIdx.y, q0 = blockIdx.x * 128;

    const char* Kg = (const char*)(Kh + (size_t)bh * TSEQ * 64);
    const char* Vg = (const char*)(Vh + (size_t)bh * 64 * TSEQ);

    // ---- Load Q tile (128 rows x 128B = 16KB) into stage 0; pull fragments.
    {
        const char* Qg = (const char*)(Qh + ((size_t)bh * TSEQ + q0) * 64);
        #pragma unroll
        for (int p = 0; p < 8; p++) {
            int i = tid + p * 128;
            int row = i >> 3, c = i & 7;
            cp_async16(sb + row * 128 + ((c ^ (row & 7)) * 16), Qg + row * 128 + c * 16);
        }
        cp_commit();
        cp_wait<0>();
        __syncthreads();
    }
    uint32_t qa0[4][4], qa1[4][4];
    {
        int r0 = wid * 32 + (lane & 7) + (((lane >> 3) & 1) << 3);
        int cbit = lane >> 4;
        uint32_t b0 = sb + r0 * 128;
        uint32_t b1 = sb + (r0 + 16) * 128;
        #pragma unroll
        for (int ks = 0; ks < 4; ks++) {
            uint32_t co = (((ks * 2 + cbit) ^ (r0 & 7)) << 4);
            ldm_x4(qa0[ks], b0 + co);
            ldm_x4(qa1[ks], b1 + co);
        }
    }
    __syncthreads();   // Q consumed; stage 0 reusable

    const int rowB  = (lane & 7) + ((lane >> 4) << 3);
    const int cbitB = (lane >> 3) & 1;
    const uint32_t browoff = rowB * 128;

    float o0[8][4], o1[8][4];
    #pragma unroll
    for (int nt = 0; nt < 8; nt++)
        #pragma unroll
        for (int i = 0; i < 4; i++) { o0[nt][i] = 0.f; o1[nt][i] = 0.f; }
    float l0 = 0.f, l1 = 0.f, l2 = 0.f, l3 = 0.f;

    auto issue = [&](int it) {
        uint32_t dst = sb + (uint32_t)(it % 3) * 16384;
        const char* kg = Kg + (size_t)it * 64 * 128;
        #pragma unroll
        for (int p = 0; p < 4; p++) {
            int i = tid + p * 128;
            int row = i >> 3, c = i & 7;
            uint32_t soff = row * 128 + ((c ^ (row & 7)) * 16);
            cp_async16(dst + soff, kg + row * 128 + c * 16);
            cp_async16(dst + 8192 + soff, Vg + (size_t)row * 8192 + (size_t)it * 128 + c * 16);
        }
        cp_commit();
    };

    issue(0);
    issue(1);

    for (int it = 0; it < NTILES; it++) {
        if (it < NTILES - 1) cp_wait<1>(); else cp_wait<0>();
        __syncthreads();                   // all warps done with buffer (it-1)%3
        if (it + 2 < NTILES) issue(it + 2);

        uint32_t kbase = sb + (uint32_t)(it % 3) * 16384 + browoff;
        uint32_t vbase = kbase + 8192;

        // S = Q·K^T for both 16-row sets, f16 accumulators.
        // sh[nt][0] = (row q, cols 2c,2c+1), sh[nt][1] = (row q+8, same).
        uint32_t sh0[8][2], sh1[8][2];
        #pragma unroll
        for (int nt = 0; nt < 8; nt++) {
            sh0[nt][0] = 0u; sh0[nt][1] = 0u;
            sh1[nt][0] = 0u; sh1[nt][1] = 0u;
        }

        #pragma unroll
        for (int ks = 0; ks < 4; ks++) {
            uint32_t coff = (((ks * 2 + cbitB) ^ (lane & 7)) << 4);
            #pragma unroll
            for (int nt2 = 0; nt2 < 4; nt2++) {
                uint32_t bfr[4];
                ldm_x4(bfr, kbase + nt2 * 2048 + coff);
                mma_f16acc(sh0[nt2 * 2 + 0], qa0[ks], bfr[0], bfr[1]);
                mma_f16acc(sh0[nt2 * 2 + 1], qa0[ks], bfr[2], bfr[3]);
                mma_f16acc(sh1[nt2 * 2 + 0], qa1[ks], bfr[0], bfr[1]);
                mma_f16acc(sh1[nt2 * 2 + 1], qa1[ks], bfr[2], bfr[3]);
            }
        }

        // P = 2^S: ex2 directly on the packed f16 D regs -> A fragments.
        // pa[jt] = {row q k-lo, row q+8 k-lo, row q k-hi, row q+8 k-hi}
        uint32_t pa0[4][4], pa1[4][4];
        #pragma unroll
        for (int jt = 0; jt < 4; jt++) {
            pa0[jt][0] = ex2_f16x2(sh0[2*jt][0]);
            pa0[jt][1] = ex2_f16x2(sh0[2*jt][1]);
            pa0[jt][2] = ex2_f16x2(sh0[2*jt+1][0]);
            pa0[jt][3] = ex2_f16x2(sh0[2*jt+1][1]);
            pa1[jt][0] = ex2_f16x2(sh1[2*jt][0]);
            pa1[jt][1] = ex2_f16x2(sh1[2*jt][1]);
            pa1[jt][2] = ex2_f16x2(sh1[2*jt+1][0]);
            pa1[jt][3] = ex2_f16x2(sh1[2*jt+1][1]);
        }
        {
            uint32_t a0 = hadd2(hadd2(pa0[0][0], pa0[1][0]), hadd2(pa0[2][0], pa0[3][0]));
            uint32_t a0b = hadd2(hadd2(pa0[0][2], pa0[1][2]), hadd2(pa0[2][2], pa0[3][2]));
            uint32_t a1 = hadd2(hadd2(pa0[0][1], pa0[1][1]), hadd2(pa0[2][1], pa0[3][1]));
            uint32_t a1b = hadd2(hadd2(pa0[0][3], pa0[1][3]), hadd2(pa0[2][3], pa0[3][3]));
            __half2 h0 = __hadd2(*(__half2*)&a0, *(__half2*)&a0b);
            __half2 h1 = __hadd2(*(__half2*)&a1, *(__half2*)&a1b);
            l0 += __low2float(h0) + __high2float(h0);
            l1 += __low2float(h1) + __high2float(h1);
            uint32_t c0 = hadd2(hadd2(pa1[0][0], pa1[1][0]), hadd2(pa1[2][0], pa1[3][0]));
            uint32_t c0b = hadd2(hadd2(pa1[0][2], pa1[1][2]), hadd2(pa1[2][2], pa1[3][2]));
            uint32_t c1 = hadd2(hadd2(pa1[0][1], pa1[1][1]), hadd2(pa1[2][1], pa1[3][1]));
            uint32_t c1b = hadd2(hadd2(pa1[0][3], pa1[1][3]), hadd2(pa1[2][3], pa1[3][3]));
            __half2 h2 = __hadd2(*(__half2*)&c0, *(__half2*)&c0b);
            __half2 h3 = __hadd2(*(__half2*)&c1, *(__half2*)&c1b);
            l2 += __low2float(h2) + __high2float(h2);
            l3 += __low2float(h3) + __high2float(h3);
        }

        // O += P·V^T for both sets (fp32 acc), sharing each V fragment
        #pragma unroll
        for (int jt = 0; jt < 4; jt++) {
            uint32_t coff = (((jt * 2 + cbitB) ^ (lane & 7)) << 4);
            #pragma unroll
            for (int nt2 = 0; nt2 < 4; nt2++) {
                uint32_t bfr[4];
                ldm_x4(bfr, vbase + nt2 * 2048 + coff);
                mma_f16(o0[nt2 * 2 + 0], pa0[jt], bfr[0], bfr[1]);
                mma_f16(o0[nt2 * 2 + 1], pa0[jt], bfr[2], bfr[3]);
                mma_f16(o1[nt2 * 2 + 0], pa1[jt], bfr[0], bfr[1]);
                mma_f16(o1[nt2 * 2 + 1], pa1[jt], bfr[2], bfr[3]);
            }
        }
    }

    // Quad reduce, normalize, store hT fp16 from fragments.
    #pragma unroll
    for (int off = 1; off <= 2; off <<= 1) {
        l0 += __shfl_xor_sync(0xffffffffu, l0, off);
        l1 += __shfl_xor_sync(0xffffffffu, l1, off);
        l2 += __shfl_xor_sync(0xffffffffu, l2, off);
        l3 += __shfl_xor_sync(0xffffffffu, l3, off);
    }
    float inv0 = 1.f / l0, inv1 = 1.f / l1, inv2 = 1.f / l2, inv3 = 1.f / l3;

    __half* hp = houtT + ((size_t)(bh >> 2) * TSEQ + q0) * CDIM + (bh & 3) * 64;
    int q  = wid * 32 + (lane >> 2);
    int cc = (lane & 3) * 2;
    #pragma unroll
    for (int nt = 0; nt < 8; nt++) {
        int d0 = nt * 8 + cc;
        *(uint32_t*)&hp[(size_t)q * CDIM + d0] =
            pack_f16x2(o0[nt][0] * inv0, o0[nt][1] * inv0);
        *(uint32_t*)&hp[(size_t)(q + 8) * CDIM + d0] =
            pack_f16x2(o0[nt][2] * inv1, o0[nt][3] * inv1);
        *(uint32_t*)&hp[(size_t)(q + 16) * CDIM + d0] =
            pack_f16x2(o1[nt][0] * inv2, o1[nt][1] * inv2);
        *(uint32_t*)&hp[(size_t)(q + 24) * CDIM + d0] =
            pack_f16x2(o1[nt][2] * inv3, o1[nt][3] * inv3);
    }
}

// ---------------------------------------------------------------------------
// Launch
// ---------------------------------------------------------------------------
extern "C" void kernel_launch(void* const* d_in, const int* in_sizes, int n_in,
                              void* d_out, int out_size) {
    const float* x      = (const float*)d_in[0];
    const float* gn_w   = (const float*)d_in[1];
    const float* gn_b   = (const float*)d_in[2];
    const float* qkv_w  = (const float*)d_in[3];
    const float* qkv_b  = (const float*)d_in[4];
    const float* proj_w = (const float*)d_in[5];
    const float* proj_b = (const float*)d_in[6];
    float* out = (float*)d_out;

    __half *xnh, *hh, *qh, *kh, *vh;
    cudaGetSymbolAddress((void**)&xnh, g_xnh);
    cudaGetSymbolAddress((void**)&hh,  g_hh);
    cudaGetSymbolAddress((void**)&qh,  g_qh);
    cudaGetSymbolAddress((void**)&kh,  g_kh);
    cudaGetSymbolAddress((void**)&vh,  g_vh);

    gn_stats_kernel<<<64, 256>>>(x);
    wconv_kernel<<<768, 256>>>(qkv_w, proj_w);
    gn_apply_t_kernel<<<dim3(4, 64, 2), 256>>>(x, gn_w, gn_b);
    gemm_qkv_h<<<dim3(32, 12, 2), 128>>>(xnh, qkv_b);
    attn_mma_kernel<<<dim3(32, 8), 128>>>(qh, kh, vh, hh);
    gemm_proj_h<<<dim3(32, 4, 2), 128>>>(hh, proj_b, x, out);
}

// round 11
// speedup vs baseline: 1.1431x; 1.1431x over previous
#include <cuda_runtime.h>
#include <cuda_fp16.h>
#include <math.h>
#include <cstdint>

// ---------------------------------------------------------------------------
// Problem constants
// ---------------------------------------------------------------------------
static constexpr int BATCH = 2;
static constexpr int CDIM  = 256;
static constexpr int TSEQ  = 4096;   // 64*64
// 64^-0.25 * sqrt(log2(e)) : folds the exp->exp2 conversion into Q and K
static constexpr float QK_SCALE = 0.42466090936113257f;
static constexpr int NTILES = TSEQ / 64;  // 64 kv tiles of 64 keys

// Scratch (device globals; allocation-free)
__device__ __half g_xnh[BATCH * TSEQ * CDIM];  // GN out, [b][t][c] 4 MB
__device__ __half g_hh [BATCH * TSEQ * CDIM];  // attn out, [b][t][c] 4 MB
__device__ __half g_qh[8 * TSEQ * 64];         // [bh][t][c] 4 MB
__device__ __half g_kh[8 * TSEQ * 64];         // [bh][t][c] 4 MB
__device__ __half g_vh[8 * 64 * TSEQ];         // [bh][d][t] 4 MB
__device__ __half g_wqkvh[768 * 256];          // fp16 qkv weight
__device__ __half g_wprojh[256 * 256];         // fp16 proj weight
__device__ float g_mean[64];
__device__ float g_rstd[64];

// ---------------------------------------------------------------------------
// PTX helpers (sm_80+ subset: mma.sync / ldmatrix / cp.async)
// ---------------------------------------------------------------------------
__device__ __forceinline__ uint32_t smem_to_u32(const void* p) {
    uint32_t a;
    asm("{ .reg .u64 t; cvta.to.shared.u64 t, %1; cvt.u32.u64 %0, t; }" : "=r"(a) : "l"(p));
    return a;
}

__device__ __forceinline__ void cp_async16(uint32_t saddr, const void* gaddr) {
    asm volatile("cp.async.cg.shared.global [%0], [%1], 16;" :: "r"(saddr), "l"(gaddr));
}
__device__ __forceinline__ void cp_commit() { asm volatile("cp.async.commit_group;"); }
template <int N>
__device__ __forceinline__ void cp_wait() { asm volatile("cp.async.wait_group %0;" :: "n"(N)); }

__device__ __forceinline__ void ldm_x4(uint32_t* r, uint32_t addr) {
    asm volatile("ldmatrix.sync.aligned.m8n8.x4.shared.b16 {%0,%1,%2,%3}, [%4];"
        : "=r"(r[0]), "=r"(r[1]), "=r"(r[2]), "=r"(r[3]) : "r"(addr));
}

__device__ __forceinline__ void mma_f16(float* c, const uint32_t* a, uint32_t b0, uint32_t b1) {
    asm volatile("mma.sync.aligned.m16n8k16.row.col.f32.f16.f16.f32 "
        "{%0,%1,%2,%3}, {%4,%5,%6,%7}, {%8,%9}, {%0,%1,%2,%3};"
        : "+f"(c[0]), "+f"(c[1]), "+f"(c[2]), "+f"(c[3])
        : "r"(a[0]), "r"(a[1]), "r"(a[2]), "r"(a[3]), "r"(b0), "r"(b1));
}

// f16 accumulator variant: D/C are 2 packed f16x2 regs.
// c[0] = (row r, cols 2c,2c+1), c[1] = (row r+8, cols 2c,2c+1)
__device__ __forceinline__ void mma_f16acc(uint32_t* c, const uint32_t* a, uint32_t b0, uint32_t b1) {
    asm volatile("mma.sync.aligned.m16n8k16.row.col.f16.f16.f16.f16 "
        "{%0,%1}, {%2,%3,%4,%5}, {%6,%7}, {%0,%1};"
        : "+r"(c[0]), "+r"(c[1])
        : "r"(a[0]), "r"(a[1]), "r"(a[2]), "r"(a[3]), "r"(b0), "r"(b1));
}

__device__ __forceinline__ uint32_t pack_f16x2(float lo, float hi) {
    uint32_t r;
    asm("cvt.rn.f16x2.f32 %0, %1, %2;" : "=r"(r) : "f"(hi), "f"(lo));
    return r;
}
__device__ __forceinline__ uint32_t ex2_f16x2(uint32_t a) {
    uint32_t r;
    asm("ex2.approx.f16x2 %0, %1;" : "=r"(r) : "r"(a));
    return r;
}
__device__ __forceinline__ uint32_t hadd2(uint32_t a, uint32_t b) {
    uint32_t r;
    asm("add.f16x2 %0, %1, %2;" : "=r"(r) : "r"(a), "r"(b));
    return r;
}

// ---------------------------------------------------------------------------
// GroupNorm stats: one block per (batch, group)
// ---------------------------------------------------------------------------
__global__ void gn_stats_kernel(const float* __restrict__ x) {
    int bg = blockIdx.x;
    const float4* p = (const float4*)(x + (size_t)bg * 32768);
    float s = 0.f, s2 = 0.f;
    for (int i = threadIdx.x; i < 8192; i += 256) {
        float4 v = p[i];
        s  += v.x + v.y + v.z + v.w;
        s2 += v.x*v.x + v.y*v.y + v.z*v.z + v.w*v.w;
    }
    #pragma unroll
    for (int off = 16; off; off >>= 1) {
        s  += __shfl_xor_sync(0xffffffffu, s,  off);
        s2 += __shfl_xor_sync(0xffffffffu, s2, off);
    }
    __shared__ float as[8], bs[8];
    int w = threadIdx.x >> 5, lane = threadIdx.x & 31;
    if (lane == 0) { as[w] = s; bs[w] = s2; }
    __syncthreads();
    if (threadIdx.x == 0) {
        float ts = 0.f, t2 = 0.f;
        #pragma unroll
        for (int i = 0; i < 8; i++) { ts += as[i]; t2 += bs[i]; }
        float mu  = ts * (1.f / 32768.f);
        float var = t2 * (1.f / 32768.f) - mu * mu;
        g_mean[bg] = mu;
        g_rstd[bg] = rsqrtf(var + 1e-5f);
    }
}

// ---------------------------------------------------------------------------
// GroupNorm apply + transpose: x [b][c][t] fp32 -> g_xnh [b][t][c] fp16.
// ---------------------------------------------------------------------------
__global__ void gn_apply_t_kernel(const float* __restrict__ x,
                                  const float* __restrict__ w,
                                  const float* __restrict__ b) {
    __shared__ float tile[64][68];
    int b_ = blockIdx.z, c0 = blockIdx.x * 64, t0 = blockIdx.y * 64;

    #pragma unroll
    for (int p = 0; p < 4; p++) {
        int i = threadIdx.x + p * 256;
        int c = i >> 4, t4 = (i & 15) * 4;
        int cg = c0 + c;
        int bg = b_ * 32 + (cg >> 3);
        float sw = w[cg] * g_rstd[bg];
        float sb = b[cg] - g_mean[bg] * sw;
        float4 v = *(const float4*)&x[((size_t)(b_ * CDIM + cg)) * TSEQ + t0 + t4];
        tile[c][t4 + 0] = v.x * sw + sb;
        tile[c][t4 + 1] = v.y * sw + sb;
        tile[c][t4 + 2] = v.z * sw + sb;
        tile[c][t4 + 3] = v.w * sw + sb;
    }
    __syncthreads();

    #pragma unroll
    for (int p = 0; p < 8; p++) {
        int i = threadIdx.x + p * 256;
        int t = i >> 5, cp = (i & 31) * 2;
        uint32_t u = pack_f16x2(tile[cp][t], tile[cp + 1][t]);
        *(uint32_t*)&g_xnh[((size_t)(b_ * TSEQ + t0 + t)) * CDIM + c0 + cp] = u;
    }
}

// ---------------------------------------------------------------------------
// Weight fp32 -> fp16
// ---------------------------------------------------------------------------
__global__ void wconv_kernel(const float* __restrict__ qkvw,
                             const float* __restrict__ projw) {
    int idx = blockIdx.x * 256 + threadIdx.x;   // 0..196607
    g_wqkvh[idx] = __float2half(qkvw[idx]);
    if (idx < 65536) g_wprojh[idx] = __float2half(projw[idx]);
}

// ---------------------------------------------------------------------------
// Shared fp16 TN GEMM mainloop, 128(t) x 64(o) tile, 4 warps x 32 t-rows:
// each B ldmatrix feeds FOUR MMAs (two A-fragment sets). K=256 in 4
// double-buffered cp.async chunks of 64. Stage = A 16KB + B 8KB = 24KB.
// ---------------------------------------------------------------------------
__device__ __forceinline__ void gemm_mainloop2(
    uint32_t sb, const char* Ag, const char* Bg,
    float (*s0)[4], float (*s1)[4]) {
    const int tid = threadIdx.x, lane = tid & 31, wid = tid >> 5;
    const int r0    = wid * 32 + (lane & 7) + (((lane >> 3) & 1) << 3);
    const int cbitA = lane >> 4;
    const int rowB  = (lane & 7) + ((lane >> 4) << 3);
    const int cbitB = (lane >> 3) & 1;
    const uint32_t brow = rowB * 128;

    #pragma unroll
    for (int nt = 0; nt < 8; nt++)
        #pragma unroll
        for (int i = 0; i < 4; i++) { s0[nt][i] = 0.f; s1[nt][i] = 0.f; }

    auto issue = [&](int kc) {
        uint32_t dst = sb + (uint32_t)(kc & 1) * 24576;
        #pragma unroll
        for (int p = 0; p < 8; p++) {                 // A: 128 rows x 128B
            int i = tid + p * 128;
            int row = i >> 3, c = i & 7;
            uint32_t soff = row * 128 + ((c ^ (row & 7)) * 16);
            cp_async16(dst + soff, Ag + (size_t)row * 512 + kc * 128 + c * 16);
        }
        #pragma unroll
        for (int p = 0; p < 4; p++) {                 // B: 64 rows x 128B
            int i = tid + p * 128;
            int row = i >> 3, c = i & 7;
            uint32_t soff = row * 128 + ((c ^ (row & 7)) * 16);
            cp_async16(dst + 16384 + soff, Bg + (size_t)row * 512 + kc * 128 + c * 16);
        }
        cp_commit();
    };

    issue(0);
    #pragma unroll
    for (int kc = 0; kc < 4; kc++) {
        if (kc < 3) { issue(kc + 1); cp_wait<1>(); } else { cp_wait<0>(); }
        __syncthreads();
        uint32_t abase = sb + (uint32_t)(kc & 1) * 24576;
        uint32_t a0 = abase + r0 * 128;
        uint32_t a1 = abase + (r0 + 16) * 128;        // (r0+16)&7 == r0&7
        uint32_t kbase = abase + 16384 + brow;
        #pragma unroll
        for (int ks = 0; ks < 4; ks++) {
            uint32_t qa0[4], qa1[4];
            uint32_t co = (((ks * 2 + cbitA) ^ (r0 & 7)) << 4);
            ldm_x4(qa0, a0 + co);
            ldm_x4(qa1, a1 + co);
            uint32_t coffB = (((ks * 2 + cbitB) ^ (lane & 7)) << 4);
            #pragma unroll
            for (int nt2 = 0; nt2 < 4; nt2++) {
                uint32_t bfr[4];
                ldm_x4(bfr, kbase + nt2 * 2048 + coffB);
                mma_f16(s0[nt2 * 2 + 0], qa0, bfr[0], bfr[1]);
                mma_f16(s0[nt2 * 2 + 1], qa0, bfr[2], bfr[3]);
                mma_f16(s1[nt2 * 2 + 0], qa1, bfr[0], bfr[1]);
                mma_f16(s1[nt2 * 2 + 1], qa1, bfr[2], bfr[3]);
            }
        }
        __syncthreads();
    }
}

// ---------------------------------------------------------------------------
// QKV GEMM: 128t x 64o tiles. Epilogue routes to Q/K [bh][t][c] (scaled)
// directly from fragments, or V [bh][d][t] via smem transpose.
// ---------------------------------------------------------------------------
__global__ void __launch_bounds__(128)
gemm_qkv_h(const __half* __restrict__ Xt, const float* __restrict__ bias) {
    __shared__ __align__(128) char sm[49152];
    uint32_t sb = smem_to_u32(sm);
    int b_ = blockIdx.z, t0 = blockIdx.x * 128, o0 = blockIdx.y * 64;

    float s0[8][4], s1[8][4];
    gemm_mainloop2(sb,
        (const char*)(Xt + ((size_t)b_ * TSEQ + t0) * CDIM),
        (const char*)(g_wqkvh + (size_t)o0 * CDIM), s0, s1);

    const int lane = threadIdx.x & 31, wid = threadIdx.x >> 5;
    int q   = wid * 32 + (lane >> 2);
    int cc2 = (lane & 3) * 2;

    int h    = o0 / 192;
    int type = (o0 % 192) / 64;   // 0=Q 1=K 2=V
    int bh   = b_ * 4 + h;

    if (type < 2) {
        __half* dst = ((type == 0) ? g_qh : g_kh) + ((size_t)bh * TSEQ + t0) * 64;
        #pragma unroll
        for (int nt = 0; nt < 8; nt++) {
            int ol = nt * 8 + cc2;
            float b0 = bias[o0 + ol], b1 = bias[o0 + ol + 1];
            *(uint32_t*)&dst[(size_t)q * 64 + ol] =
                pack_f16x2((s0[nt][0] + b0) * QK_SCALE, (s0[nt][1] + b1) * QK_SCALE);
            *(uint32_t*)&dst[(size_t)(q + 8) * 64 + ol] =
                pack_f16x2((s0[nt][2] + b0) * QK_SCALE, (s0[nt][3] + b1) * QK_SCALE);
            *(uint32_t*)&dst[(size_t)(q + 16) * 64 + ol] =
                pack_f16x2((s1[nt][0] + b0) * QK_SCALE, (s1[nt][1] + b1) * QK_SCALE);
            *(uint32_t*)&dst[(size_t)(q + 24) * 64 + ol] =
                pack_f16x2((s1[nt][2] + b0) * QK_SCALE, (s1[nt][3] + b1) * QK_SCALE);
        }
    } else {
        __half (*sv)[136] = (__half(*)[136])sm;   // [64 o][128 t + pad]
        #pragma unroll
        for (int nt = 0; nt < 8; nt++) {
            int ol = nt * 8 + cc2;
            float b0 = bias[o0 + ol], b1 = bias[o0 + ol + 1];
            sv[ol][q]          = __float2half(s0[nt][0] + b0);
            sv[ol + 1][q]      = __float2half(s0[nt][1] + b1);
            sv[ol][q + 8]      = __float2half(s0[nt][2] + b0);
            sv[ol + 1][q + 8]  = __float2half(s0[nt][3] + b1);
            sv[ol][q + 16]     = __float2half(s1[nt][0] + b0);
            sv[ol + 1][q + 16] = __float2half(s1[nt][1] + b1);
            sv[ol][q + 24]     = __float2half(s1[nt][2] + b0);
            sv[ol + 1][q + 24] = __float2half(s1[nt][3] + b1);
        }
        __syncthreads();
        for (int i = threadIdx.x; i < 4096; i += 128) {
            int d = i >> 6, tp = (i & 63) * 2;
            uint32_t u = pack_f16x2(__half2float(sv[d][tp]), __half2float(sv[d][tp + 1]));
            *(uint32_t*)&g_vh[((size_t)bh * 64 + d) * TSEQ + t0 + tp] = u;
        }
    }
}

// ---------------------------------------------------------------------------
// Proj GEMM: 128t x 64o tiles + bias + residual, fp32 out [b][o][t].
// ---------------------------------------------------------------------------
__global__ void __launch_bounds__(128)
gemm_proj_h(const __half* __restrict__ Ht, const float* __restrict__ bias,
            const float* __restrict__ R, float* __restrict__ Y) {
    __shared__ __align__(128) char sm[49152];
    uint32_t sb = smem_to_u32(sm);
    int b_ = blockIdx.z, t0 = blockIdx.x * 128, o0 = blockIdx.y * 64;

    float s0[8][4], s1[8][4];
    gemm_mainloop2(sb,
        (const char*)(Ht + ((size_t)b_ * TSEQ + t0) * CDIM),
        (const char*)(g_wprojh + (size_t)o0 * CDIM), s0, s1);

    const int lane = threadIdx.x & 31, wid = threadIdx.x >> 5;
    int q   = wid * 32 + (lane >> 2);
    int cc2 = (lane & 3) * 2;

    float (*so)[132] = (float(*)[132])sm;   // [64 o][128 t + pad]
    #pragma unroll
    for (int nt = 0; nt < 8; nt++) {
        int ol = nt * 8 + cc2;
        so[ol][q]          = s0[nt][0];
        so[ol + 1][q]      = s0[nt][1];
        so[ol][q + 8]      = s0[nt][2];
        so[ol + 1][q + 8]  = s0[nt][3];
        so[ol][q + 16]     = s1[nt][0];
        so[ol + 1][q + 16] = s1[nt][1];
        so[ol][q + 24]     = s1[nt][2];
        so[ol + 1][q + 24] = s1[nt][3];
    }
    __syncthreads();
    for (int i = threadIdx.x; i < 2048; i += 128) {
        int o = i >> 5, t4 = (i & 31) * 4;
        size_t idx = ((size_t)(b_ * CDIM + o0 + o)) * TSEQ + t0 + t4;
        float4 rv = *(const float4*)&R[idx];
        float bvv = bias[o0 + o];
        float4 r;
        r.x = so[o][t4 + 0] + bvv + rv.x;
        r.y = so[o][t4 + 1] + bvv + rv.y;
        r.z = so[o][t4 + 2] + bvv + rv.z;
        r.w = so[o][t4 + 3] + bvv + rv.w;
        *(float4*)&Y[idx] = r;
    }
}

// ---------------------------------------------------------------------------
// Flash attention, fp16 mma.sync. 128-query tile, 4 warps, 32 q-rows/warp.
// S-GEMM uses f16 accumulators: D comes back packed f16x2 in exactly the
// P·V^T A-fragment layout, so softmax is just ex2.approx.f16x2 on the D regs
// (no cvt packs). O stays fp32. 3-stage cp.async pipeline, one sync/iter.
// Occupancy bound 2 (bound 3 caused register spills in R10).
// ---------------------------------------------------------------------------
__global__ void __launch_bounds__(128, 2)
attn_mma_kernel(const __half* __restrict__ Qh,
                const __half* __restrict__ Kh,
                const __half* __restrict__ Vh,
                __half* __restrict__ houtT) {
    __shared__ __align__(128) char smem[49152];   // 3 stages x 16 KB
    uint32_t sb = smem_to_u32(smem);
    const int tid = threadIdx.x, lane = tid & 31, wid = tid >> 5;
    const int bh = blockIdx.y, q0 = blockIdx.x * 128;

    const char* Kg = (const char*)(Kh + (size_t)bh * TSEQ * 64);
    const char* Vg = (const char*)(Vh + (size_t)bh * 64 * TSEQ);

    // ---- Load Q tile (128 rows x 128B = 16KB) into stage 0; pull fragments.
    {
        const char* Qg = (const char*)(Qh + ((size_t)bh * TSEQ + q0) * 64);
        #pragma unroll
        for (int p = 0; p < 8; p++) {
            int i = tid + p * 128;
            int row = i >> 3, c = i & 7;
            cp_async16(sb + row * 128 + ((c ^ (row & 7)) * 16), Qg + row * 128 + c * 16);
        }
        cp_commit();
        cp_wait<0>();
        __syncthreads();
    }
    uint32_t qa0[4][4], qa1[4][4];
    {
        int r0 = wid * 32 + (lane & 7) + (((lane >> 3) & 1) << 3);
        int cbit = lane >> 4;
        uint32_t b0 = sb + r0 * 128;
        uint32_t b1 = sb + (r0 + 16) * 128;
        #pragma unroll
        for (int ks = 0; ks < 4; ks++) {
            uint32_t co = (((ks * 2 + cbit) ^ (r0 & 7)) << 4);
            ldm_x4(qa0[ks], b0 + co);
            ldm_x4(qa1[ks], b1 + co);
        }
    }
    __syncthreads();   // Q consumed; stage 0 reusable

    const int rowB  = (lane & 7) + ((lane >> 4) << 3);
    const int cbitB = (lane >> 3) & 1;
    const uint32_t browoff = rowB * 128;

    float o0[8][4], o1[8][4];
    #pragma unroll
    for (int nt = 0; nt < 8; nt++)
        #pragma unroll
        for (int i = 0; i < 4; i++) { o0[nt][i] = 0.f; o1[nt][i] = 0.f; }
    float l0 = 0.f, l1 = 0.f, l2 = 0.f, l3 = 0.f;

    auto issue = [&](int it) {
        uint32_t dst = sb + (uint32_t)(it % 3) * 16384;
        const char* kg = Kg + (size_t)it * 64 * 128;
        #pragma unroll
        for (int p = 0; p < 4; p++) {
            int i = tid + p * 128;
            int row = i >> 3, c = i & 7;
            uint32_t soff = row * 128 + ((c ^ (row & 7)) * 16);
            cp_async16(dst + soff, kg + row * 128 + c * 16);
            cp_async16(dst + 8192 + soff, Vg + (size_t)row * 8192 + (size_t)it * 128 + c * 16);
        }
        cp_commit();
    };

    issue(0);
    issue(1);

    for (int it = 0; it < NTILES; it++) {
        if (it < NTILES - 1) cp_wait<1>(); else cp_wait<0>();
        __syncthreads();                   // all warps done with buffer (it-1)%3
        if (it + 2 < NTILES) issue(it + 2);

        uint32_t kbase = sb + (uint32_t)(it % 3) * 16384 + browoff;
        uint32_t vbase = kbase + 8192;

        // S = Q·K^T for both 16-row sets, f16 accumulators.
        uint32_t sh0[8][2], sh1[8][2];
        #pragma unroll
        for (int nt = 0; nt < 8; nt++) {
            sh0[nt][0] = 0u; sh0[nt][1] = 0u;
            sh1[nt][0] = 0u; sh1[nt][1] = 0u;
        }

        #pragma unroll
        for (int ks = 0; ks < 4; ks++) {
            uint32_t coff = (((ks * 2 + cbitB) ^ (lane & 7)) << 4);
            #pragma unroll
            for (int nt2 = 0; nt2 < 4; nt2++) {
                uint32_t bfr[4];
                ldm_x4(bfr, kbase + nt2 * 2048 + coff);
                mma_f16acc(sh0[nt2 * 2 + 0], qa0[ks], bfr[0], bfr[1]);
                mma_f16acc(sh0[nt2 * 2 + 1], qa0[ks], bfr[2], bfr[3]);
                mma_f16acc(sh1[nt2 * 2 + 0], qa1[ks], bfr[0], bfr[1]);
                mma_f16acc(sh1[nt2 * 2 + 1], qa1[ks], bfr[2], bfr[3]);
            }
        }

        // P = 2^S: ex2 directly on the packed f16 D regs -> A fragments.
        uint32_t pa0[4][4], pa1[4][4];
        #pragma unroll
        for (int jt = 0; jt < 4; jt++) {
            pa0[jt][0] = ex2_f16x2(sh0[2*jt][0]);
            pa0[jt][1] = ex2_f16x2(sh0[2*jt][1]);
            pa0[jt][2] = ex2_f16x2(sh0[2*jt+1][0]);
            pa0[jt][3] = ex2_f16x2(sh0[2*jt+1][1]);
            pa1[jt][0] = ex2_f16x2(sh1[2*jt][0]);
            pa1[jt][1] = ex2_f16x2(sh1[2*jt][1]);
            pa1[jt][2] = ex2_f16x2(sh1[2*jt+1][0]);
            pa1[jt][3] = ex2_f16x2(sh1[2*jt+1][1]);
        }
        {
            uint32_t a0 = hadd2(hadd2(pa0[0][0], pa0[1][0]), hadd2(pa0[2][0], pa0[3][0]));
            uint32_t a0b = hadd2(hadd2(pa0[0][2], pa0[1][2]), hadd2(pa0[2][2], pa0[3][2]));
            uint32_t a1 = hadd2(hadd2(pa0[0][1], pa0[1][1]), hadd2(pa0[2][1], pa0[3][1]));
            uint32_t a1b = hadd2(hadd2(pa0[0][3], pa0[1][3]), hadd2(pa0[2][3], pa0[3][3]));
            __half2 h0 = __hadd2(*(__half2*)&a0, *(__half2*)&a0b);
            __half2 h1 = __hadd2(*(__half2*)&a1, *(__half2*)&a1b);
            l0 += __low2float(h0) + __high2float(h0);
            l1 += __low2float(h1) + __high2float(h1);
            uint32_t c0 = hadd2(hadd2(pa1[0][0], pa1[1][0]), hadd2(pa1[2][0], pa1[3][0]));
            uint32_t c0b = hadd2(hadd2(pa1[0][2], pa1[1][2]), hadd2(pa1[2][2], pa1[3][2]));
            uint32_t c1 = hadd2(hadd2(pa1[0][1], pa1[1][1]), hadd2(pa1[2][1], pa1[3][1]));
            uint32_t c1b = hadd2(hadd2(pa1[0][3], pa1[1][3]), hadd2(pa1[2][3], pa1[3][3]));
            __half2 h2 = __hadd2(*(__half2*)&c0, *(__half2*)&c0b);
            __half2 h3 = __hadd2(*(__half2*)&c1, *(__half2*)&c1b);
            l2 += __low2float(h2) + __high2float(h2);
            l3 += __low2float(h3) + __high2float(h3);
        }

        // O += P·V^T for both sets (fp32 acc), sharing each V fragment
        #pragma unroll
        for (int jt = 0; jt < 4; jt++) {
            uint32_t coff = (((jt * 2 + cbitB) ^ (lane & 7)) << 4);
            #pragma unroll
            for (int nt2 = 0; nt2 < 4; nt2++) {
                uint32_t bfr[4];
                ldm_x4(bfr, vbase + nt2 * 2048 + coff);
                mma_f16(o0[nt2 * 2 + 0], pa0[jt], bfr[0], bfr[1]);
                mma_f16(o0[nt2 * 2 + 1], pa0[jt], bfr[2], bfr[3]);
                mma_f16(o1[nt2 * 2 + 0], pa1[jt], bfr[0], bfr[1]);
                mma_f16(o1[nt2 * 2 + 1], pa1[jt], bfr[2], bfr[3]);
            }
        }
    }

    // Quad reduce, normalize, store hT fp16 from fragments.
    #pragma unroll
    for (int off = 1; off <= 2; off <<= 1) {
        l0 += __shfl_xor_sync(0xffffffffu, l0, off);
        l1 += __shfl_xor_sync(0xffffffffu, l1, off);
        l2 += __shfl_xor_sync(0xffffffffu, l2, off);
        l3 += __shfl_xor_sync(0xffffffffu, l3, off);
    }
    float inv0 = 1.f / l0, inv1 = 1.f / l1, inv2 = 1.f / l2, inv3 = 1.f / l3;

    __half* hp = houtT + ((size_t)(bh >> 2) * TSEQ + q0) * CDIM + (bh & 3) * 64;
    int q  = wid * 32 + (lane >> 2);
    int cc = (lane & 3) * 2;
    #pragma unroll
    for (int nt = 0; nt < 8; nt++) {
        int d0 = nt * 8 + cc;
        *(uint32_t*)&hp[(size_t)q * CDIM + d0] =
            pack_f16x2(o0[nt][0] * inv0, o0[nt][1] * inv0);
        *(uint32_t*)&hp[(size_t)(q + 8) * CDIM + d0] =
            pack_f16x2(o0[nt][2] * inv1, o0[nt][3] * inv1);
        *(uint32_t*)&hp[(size_t)(q + 16) * CDIM + d0] =
            pack_f16x2(o1[nt][0] * inv2, o1[nt][1] * inv2);
        *(uint32_t*)&hp[(size_t)(q + 24) * CDIM + d0] =
            pack_f16x2(o1[nt][2] * inv3, o1[nt][3] * inv3);
    }
}

// ---------------------------------------------------------------------------
// Launch
// ---------------------------------------------------------------------------
extern "C" void kernel_launch(void* const* d_in, const int* in_sizes, int n_in,
                              void* d_out, int out_size) {
    const float* x      = (const float*)d_in[0];
    const float* gn_w   = (const float*)d_in[1];
    const float* gn_b   = (const float*)d_in[2];
    const float* qkv_w  = (const float*)d_in[3];
    const float* qkv_b  = (const float*)d_in[4];
    const float* proj_w = (const float*)d_in[5];
    const float* proj_b = (const float*)d_in[6];
    float* out = (float*)d_out;

    __half *xnh, *hh, *qh, *kh, *vh;
    cudaGetSymbolAddress((void**)&xnh, g_xnh);
    cudaGetSymbolAddress((void**)&hh,  g_hh);
    cudaGetSymbolAddress((void**)&qh,  g_qh);
    cudaGetSymbolAddress((void**)&kh,  g_kh);
    cudaGetSymbolAddress((void**)&vh,  g_vh);

    gn_stats_kernel<<<64, 256>>>(x);
    wconv_kernel<<<768, 256>>>(qkv_w, proj_w);
    gn_apply_t_kernel<<<dim3(4, 64, 2), 256>>>(x, gn_w, gn_b);
    gemm_qkv_h<<<dim3(32, 12, 2), 128>>>(xnh, qkv_b);
    attn_mma_kernel<<<dim3(32, 8), 128>>>(qh, kh, vh, hh);
    gemm_proj_h<<<dim3(32, 4, 2), 128>>>(hh, proj_b, x, out);
}